// round 4
// baseline (speedup 1.0000x reference)
#include <cuda_runtime.h>
#include <cstdint>

// ============================================================================
// out[z,k] = sum_{i,j} M[k,i,j] * f1[z,i] * f2[z,j]
// Dense tf32 warp-MMA GEMM:  out = P @ W
//   P[z, i*32+j] = f1[z,i]*f2[z,j]   (generated in registers)
//   W[i*32+j, k] = M[k,i,j]          (pre-packed to fragment order)
//
// R4: warp tile m32 x n16 (same B bytes/MMA as m32n32, but C regs 32->16),
//     launch_bounds(256,3) -> 24 warps/SM for latency hiding.
// ============================================================================

#define N_I 32
#define N_J 32
#define N_K 64
#define Z_CTA 64               // 2 m-groups x 32 rows
#define NTHREADS 256           // 8 warps = 2 m-groups x 4 n-quarters
#define N_CHUNKS 128           // K = 1024 / 8

// Packed W layout: [chunk][nq(4)][lane(32)][slot(4)], slot = nt*2 + b
//   value = tf32( M[n,i,j] ), n = nq*16 + nt*8 + qr, kk = c + 4b,
//   i = chunk/4, j = (chunk%4)*8 + kk      (lane: qr = lane/4, c = lane%4)
__device__ float g_Wp[N_CHUNKS * 512];   // 256 KB

static __device__ __forceinline__ uint32_t f32_to_tf32_rn(float x) {
    uint32_t r;
    asm("cvt.rn.tf32.f32 %0, %1;" : "=r"(r) : "f"(x));
    return r;
}

// ---------------------------------------------------------------------------
__global__ void etp_pack_kernel(const float* __restrict__ Mx) {
    int idx = blockIdx.x * blockDim.x + threadIdx.x;   // 0..65535
    int chunk = idx >> 9;
    int rem   = idx & 511;
    int nq    = rem >> 7;
    int r2    = rem & 127;
    int lane  = r2 >> 2;
    int slot  = r2 & 3;
    int nt    = slot >> 1;
    int b     = slot & 1;
    int qr    = lane >> 2;
    int c     = lane & 3;
    int n     = nq * 16 + nt * 8 + qr;
    int kk    = c + 4 * b;
    int i     = chunk >> 2;
    int j     = ((chunk & 3) << 3) + kk;
    float v = Mx[n * (N_I * N_J) + i * N_J + j];
    g_Wp[idx] = __uint_as_float(f32_to_tf32_rn(v));
}

// ---------------------------------------------------------------------------

#define MMA_TF32(cacc, a0, a1, a2, a3, b0, b1)                                \
    asm volatile(                                                             \
        "mma.sync.aligned.m16n8k8.row.col.f32.tf32.tf32.f32 "                 \
        "{%0,%1,%2,%3}, {%4,%5,%6,%7}, {%8,%9}, {%0,%1,%2,%3};"               \
        : "+f"((cacc)[0]), "+f"((cacc)[1]), "+f"((cacc)[2]), "+f"((cacc)[3])  \
        : "r"(a0), "r"(a1), "r"(a2), "r"(a3), "r"(b0), "r"(b1))

__global__ void __launch_bounds__(NTHREADS, 3)
etp_mma_kernel(const float* __restrict__ F1,
               const float* __restrict__ F2,
               float* __restrict__ Out) {
    // padded rows (36 floats) -> conflict-free column reads
    __shared__ float f1s[Z_CTA * 36];
    __shared__ float f2s[Z_CTA * 36];

    const int tid    = threadIdx.x;
    const int warp   = tid >> 5;
    const int lane   = tid & 31;
    const int mgroup = warp >> 2;        // 0..1, 32 rows each
    const int nq     = warp & 3;         // n columns [nq*16, +16)
    const int qr     = lane >> 2;        // 0..7
    const int c      = lane & 3;         // 0..3

    // ---- stage f1, f2 tiles (coalesced float4) ----
    {
        const float4* f1g = reinterpret_cast<const float4*>(
            F1 + (size_t)blockIdx.x * Z_CTA * N_I);
        const float4* f2g = reinterpret_cast<const float4*>(
            F2 + (size_t)blockIdx.x * Z_CTA * N_J);
#pragma unroll
        for (int t = 0; t < 2; t++) {
            int i4 = tid + t * NTHREADS;          // 0..511
            int row = i4 >> 3, cg = i4 & 7;
            *reinterpret_cast<float4*>(&f1s[row * 36 + cg * 4]) = __ldg(f1g + i4);
            *reinterpret_cast<float4*>(&f2s[row * 36 + cg * 4]) = __ldg(f2g + i4);
        }
    }
    __syncthreads();

    // thread's 4 z rows (local)
    const int r0 = mgroup * 32 + qr;     // rows r0, r0+8, r0+16, r0+24

    // ---- f2 slots in registers: slot s=cg*2+h -> j = 8*cg + c + 4*h ----
    float f2v[4][8];
#pragma unroll
    for (int rr = 0; rr < 4; rr++) {
#pragma unroll
        for (int s = 0; s < 8; s++) {
            int cg = s >> 1, h = s & 1;
            int j = 8 * cg + c + 4 * h;
            f2v[rr][s] = f2s[(r0 + rr * 8) * 36 + j];
        }
    }

    float C[2][2][4];                    // [mtile][ntile][quad]
#pragma unroll
    for (int mt = 0; mt < 2; mt++)
#pragma unroll
        for (int nt = 0; nt < 2; nt++)
#pragma unroll
            for (int q = 0; q < 4; q++) C[mt][nt][q] = 0.0f;

    // ---- B stream: per chunk 1x LDG.128 per lane ----
    const float4* wp = reinterpret_cast<const float4*>(g_Wp);
    const int boff = nq * 32 + lane;     // float4 units within a chunk (128)
    float4 bA = __ldg(wp + boff);

#pragma unroll 1
    for (int ig = 0; ig < N_I; ig++) {
        float f1v[4];
#pragma unroll
        for (int rr = 0; rr < 4; rr++) f1v[rr] = f1s[(r0 + rr * 8) * 36 + ig];

#pragma unroll
        for (int cc = 0; cc < 4; cc++) {
            const float4 b0 = bA;

            const int chunk = ig * 4 + cc;
            if (chunk < N_CHUNKS - 1)            // prefetch next chunk
                bA = __ldg(wp + (size_t)(chunk + 1) * 128 + boff);

            // A fragments (products), tf32-rounded
            uint32_t pr[4][2];
#pragma unroll
            for (int rr = 0; rr < 4; rr++) {
                pr[rr][0] = f32_to_tf32_rn(f1v[rr] * f2v[rr][cc * 2 + 0]);
                pr[rr][1] = f32_to_tf32_rn(f1v[rr] * f2v[rr][cc * 2 + 1]);
            }

            // mtile0: rows r0, r0+8
            MMA_TF32(C[0][0], pr[0][0], pr[1][0], pr[0][1], pr[1][1],
                     __float_as_uint(b0.x), __float_as_uint(b0.y));
            MMA_TF32(C[0][1], pr[0][0], pr[1][0], pr[0][1], pr[1][1],
                     __float_as_uint(b0.z), __float_as_uint(b0.w));
            // mtile1: rows r0+16, r0+24
            MMA_TF32(C[1][0], pr[2][0], pr[3][0], pr[2][1], pr[3][1],
                     __float_as_uint(b0.x), __float_as_uint(b0.y));
            MMA_TF32(C[1][1], pr[2][0], pr[3][0], pr[2][1], pr[3][1],
                     __float_as_uint(b0.z), __float_as_uint(b0.w));
        }
    }

    // ---- epilogue ----
    const size_t zbase = (size_t)blockIdx.x * Z_CTA;
#pragma unroll
    for (int mt = 0; mt < 2; mt++) {
        const size_t z0 = zbase + r0 + mt * 16;
        const size_t z1 = z0 + 8;
#pragma unroll
        for (int nt = 0; nt < 2; nt++) {
            const int col = nq * 16 + nt * 8 + 2 * c;
            *reinterpret_cast<float2*>(Out + z0 * N_K + col) =
                make_float2(C[mt][nt][0], C[mt][nt][1]);
            *reinterpret_cast<float2*>(Out + z1 * N_K + col) =
                make_float2(C[mt][nt][2], C[mt][nt][3]);
        }
    }
}

// ---------------------------------------------------------------------------

extern "C" void kernel_launch(void* const* d_in, const int* in_sizes, int n_in,
                              void* d_out, int out_size) {
    const float* f1 = (const float*)d_in[0];   // [Z, 32]
    const float* f2 = (const float*)d_in[1];   // [Z, 32]
    const float* mx = (const float*)d_in[2];   // [64, 32, 32]
    float* out = (float*)d_out;                // [Z, 64]

    const int z_total = in_sizes[0] / N_I;     // 131072
    const int blocks = z_total / Z_CTA;        // 2048

    etp_pack_kernel<<<256, 256>>>(mx);
    etp_mma_kernel<<<blocks, NTHREADS>>>(f1, f2, out);
}

// round 5
// speedup vs baseline: 1.5922x; 1.5922x over previous
#include <cuda_runtime.h>
#include <cstdint>

// ============================================================================
// out[z,k] = sum_{i,j} M[k,i,j] * f1[z,i] * f2[z,j]
// Dense tf32 warp-MMA GEMM:  out = P @ W
//   P[z, i*32+j] = f1[z,i]*f2[z,j]   (generated in registers)
//   W[i*32+j, k] = M[k,i,j]          (pre-packed to fragment order, tf32-RN)
//
// R5 = R3 (m32n32 warp tile, 256thr x 2 CTA/SM) +
//   - A products fed to MMA as raw f32 bits (HW reads top 19 bits; saves
//     8 cvt.rn.tf32 issue slots per 8-MMA chunk)
//   - branchless B prefetch via padded W + running pointer
// ============================================================================

#define N_I 32
#define N_J 32
#define N_K 64
#define Z_CTA 128              // 4 m-groups x 32 rows
#define NTHREADS 256           // 8 warps = 4 m-groups x 2 n-halves
#define N_CHUNKS 128           // K = 1024 / 8

// Packed W layout: [chunk][nhalf][lane][slot0..7], slot = nt*2 + b
//   value = tf32_rn( M[n, i, j] ), n = nhalf*32 + nt*8 + qr,
//   kk = c + 4b, i = chunk/4, j = (chunk%4)*8 + kk   (lane: qr=lane/4, c=lane%4)
// +1 chunk of zero padding so the prefetch of chunk 128 is always legal.
__device__ float g_Wp[(N_CHUNKS + 1) * 512];   // 258 KB

static __device__ __forceinline__ uint32_t f32_to_tf32_rn(float x) {
    uint32_t r;
    asm("cvt.rn.tf32.f32 %0, %1;" : "=r"(r) : "f"(x));
    return r;
}

// ---------------------------------------------------------------------------
__global__ void etp_pack_kernel(const float* __restrict__ Mx) {
    int idx = blockIdx.x * blockDim.x + threadIdx.x;   // 0..66047
    if (idx >= N_CHUNKS * 512) {                       // zero the pad chunk
        g_Wp[idx] = 0.0f;
        return;
    }
    int chunk = idx >> 9;
    int rem   = idx & 511;
    int nhalf = rem >> 8;
    int r2    = rem & 255;
    int lane  = r2 >> 3;
    int slot  = r2 & 7;
    int nt    = slot >> 1;
    int b     = slot & 1;
    int qr    = lane >> 2;
    int c     = lane & 3;
    int n     = nhalf * 32 + nt * 8 + qr;
    int kk    = c + 4 * b;
    int i     = chunk >> 2;
    int j     = ((chunk & 3) << 3) + kk;
    float v = Mx[n * (N_I * N_J) + i * N_J + j];
    g_Wp[idx] = __uint_as_float(f32_to_tf32_rn(v));
}

// ---------------------------------------------------------------------------

#define MMA_TF32(cacc, a0, a1, a2, a3, b0, b1)                                \
    asm volatile(                                                             \
        "mma.sync.aligned.m16n8k8.row.col.f32.tf32.tf32.f32 "                 \
        "{%0,%1,%2,%3}, {%4,%5,%6,%7}, {%8,%9}, {%0,%1,%2,%3};"               \
        : "+f"((cacc)[0]), "+f"((cacc)[1]), "+f"((cacc)[2]), "+f"((cacc)[3])  \
        : "r"(a0), "r"(a1), "r"(a2), "r"(a3), "r"(b0), "r"(b1))

__global__ void __launch_bounds__(NTHREADS, 2)
etp_mma_kernel(const float* __restrict__ F1,
               const float* __restrict__ F2,
               float* __restrict__ Out) {
    // padded rows (36 floats) -> conflict-free column reads
    __shared__ float f1s[Z_CTA * 36];
    __shared__ float f2s[Z_CTA * 36];

    const int tid    = threadIdx.x;
    const int warp   = tid >> 5;
    const int lane   = tid & 31;
    const int mgroup = warp >> 1;        // 0..3, 32 rows each
    const int nhalf  = warp & 1;         // n columns [nhalf*32, +32)
    const int qr     = lane >> 2;        // 0..7
    const int c      = lane & 3;         // 0..3

    // ---- stage f1, f2 tiles (coalesced float4) ----
    {
        const float4* f1g = reinterpret_cast<const float4*>(
            F1 + (size_t)blockIdx.x * Z_CTA * N_I);
        const float4* f2g = reinterpret_cast<const float4*>(
            F2 + (size_t)blockIdx.x * Z_CTA * N_J);
#pragma unroll
        for (int t = 0; t < 4; t++) {
            int i4 = tid + t * NTHREADS;          // 0..1023
            int row = i4 >> 3, cg = i4 & 7;
            *reinterpret_cast<float4*>(&f1s[row * 36 + cg * 4]) = __ldg(f1g + i4);
            *reinterpret_cast<float4*>(&f2s[row * 36 + cg * 4]) = __ldg(f2g + i4);
        }
    }
    __syncthreads();

    // thread's 4 z rows (local)
    const int r0 = mgroup * 32 + qr;     // rows r0, r0+8, r0+16, r0+24

    // ---- f2 slots in registers: slot s=cg*2+h -> j = 8*cg + c + 4*h ----
    float f2v[4][8];
#pragma unroll
    for (int rr = 0; rr < 4; rr++) {
#pragma unroll
        for (int s = 0; s < 8; s++) {
            int cg = s >> 1, h = s & 1;
            int j = 8 * cg + c + 4 * h;
            f2v[rr][s] = f2s[(r0 + rr * 8) * 36 + j];
        }
    }

    float C[2][4][4];                    // [mtile][ntile][quad]
#pragma unroll
    for (int mt = 0; mt < 2; mt++)
#pragma unroll
        for (int nt = 0; nt < 4; nt++)
#pragma unroll
            for (int q = 0; q < 4; q++) C[mt][nt][q] = 0.0f;

    // ---- B stream: 2x LDG.128 per lane per chunk, running pointer ----
    const float4* wq = reinterpret_cast<const float4*>(g_Wp)
                       + nhalf * 64 + lane * 2;
    float4 bA = __ldg(wq);
    float4 bB = __ldg(wq + 1);

#pragma unroll 1
    for (int ig = 0; ig < N_I; ig++) {
        float f1v[4];
#pragma unroll
        for (int rr = 0; rr < 4; rr++) f1v[rr] = f1s[(r0 + rr * 8) * 36 + ig];

#pragma unroll
        for (int cc = 0; cc < 4; cc++) {
            const float4 b0 = bA, b1 = bB;

            wq += 128;                           // next chunk (pad makes last legal)
            bA = __ldg(wq);
            bB = __ldg(wq + 1);

            // A fragments: raw f32 product bits (HW truncates to tf32)
            uint32_t pr[4][2];
#pragma unroll
            for (int rr = 0; rr < 4; rr++) {
                pr[rr][0] = __float_as_uint(f1v[rr] * f2v[rr][cc * 2 + 0]);
                pr[rr][1] = __float_as_uint(f1v[rr] * f2v[rr][cc * 2 + 1]);
            }

            // mtile0: rows r0, r0+8
            MMA_TF32(C[0][0], pr[0][0], pr[1][0], pr[0][1], pr[1][1],
                     __float_as_uint(b0.x), __float_as_uint(b0.y));
            MMA_TF32(C[0][1], pr[0][0], pr[1][0], pr[0][1], pr[1][1],
                     __float_as_uint(b0.z), __float_as_uint(b0.w));
            MMA_TF32(C[0][2], pr[0][0], pr[1][0], pr[0][1], pr[1][1],
                     __float_as_uint(b1.x), __float_as_uint(b1.y));
            MMA_TF32(C[0][3], pr[0][0], pr[1][0], pr[0][1], pr[1][1],
                     __float_as_uint(b1.z), __float_as_uint(b1.w));
            // mtile1: rows r0+16, r0+24
            MMA_TF32(C[1][0], pr[2][0], pr[3][0], pr[2][1], pr[3][1],
                     __float_as_uint(b0.x), __float_as_uint(b0.y));
            MMA_TF32(C[1][1], pr[2][0], pr[3][0], pr[2][1], pr[3][1],
                     __float_as_uint(b0.z), __float_as_uint(b0.w));
            MMA_TF32(C[1][2], pr[2][0], pr[3][0], pr[2][1], pr[3][1],
                     __float_as_uint(b1.x), __float_as_uint(b1.y));
            MMA_TF32(C[1][3], pr[2][0], pr[3][0], pr[2][1], pr[3][1],
                     __float_as_uint(b1.z), __float_as_uint(b1.w));
        }
    }

    // ---- epilogue ----
    const size_t zbase = (size_t)blockIdx.x * Z_CTA;
#pragma unroll
    for (int mt = 0; mt < 2; mt++) {
        const size_t z0 = zbase + r0 + mt * 16;
        const size_t z1 = z0 + 8;
#pragma unroll
        for (int nt = 0; nt < 4; nt++) {
            const int col = nhalf * 32 + nt * 8 + 2 * c;
            *reinterpret_cast<float2*>(Out + z0 * N_K + col) =
                make_float2(C[mt][nt][0], C[mt][nt][1]);
            *reinterpret_cast<float2*>(Out + z1 * N_K + col) =
                make_float2(C[mt][nt][2], C[mt][nt][3]);
        }
    }
}

// ---------------------------------------------------------------------------

extern "C" void kernel_launch(void* const* d_in, const int* in_sizes, int n_in,
                              void* d_out, int out_size) {
    const float* f1 = (const float*)d_in[0];   // [Z, 32]
    const float* f2 = (const float*)d_in[1];   // [Z, 32]
    const float* mx = (const float*)d_in[2];   // [64, 32, 32]
    float* out = (float*)d_out;                // [Z, 64]

    const int z_total = in_sizes[0] / N_I;     // 131072
    const int blocks = z_total / Z_CTA;        // 1024

    etp_pack_kernel<<<259, 256>>>(mx);         // 259*256 >= 66048 (incl. pad)
    etp_mma_kernel<<<blocks, NTHREADS>>>(f1, f2, out);
}

// round 6
// speedup vs baseline: 1.6800x; 1.0552x over previous
#include <cuda_runtime.h>
#include <cstdint>

// ============================================================================
// out[z,k] = sum_{i,j} M[k,i,j] * f1[z,i] * f2[z,j]
// Dense tf32 warp-MMA GEMM:  out = P @ W
//   P[z, i*32+j] = f1[z,i]*f2[z,j]   (generated in registers)
//   W[i*32+j, k] = M[k,i,j]          (pre-packed to fragment order, tf32-RN)
//
// R6 = R5 + lane-contiguous B packing:
//   old: [chunk][nhalf][lane][slot0..7]  -> LDG.128 lane stride 32B = 8 wf
//   new: [chunk][nhalf][pair][lane][4]   -> LDG.128 lane stride 16B = 4 wf
//   (halves L1 wavefronts of the B stream; bytes & math identical)
// ============================================================================

#define N_I 32
#define N_J 32
#define N_K 64
#define Z_CTA 128              // 4 m-groups x 32 rows
#define NTHREADS 256           // 8 warps = 4 m-groups x 2 n-halves
#define N_CHUNKS 128           // K = 1024 / 8

// Packed W: float4 unit offset = chunk*128 + nhalf*64 + pair*32 + lane
//   pair 0 holds slots 0..3 (n-tiles 0,1), pair 1 holds slots 4..7 (n-tiles 2,3)
//   slot = nt*2 + b ; value = tf32_rn(M[n,i,j]),
//   n = nhalf*32 + nt*8 + qr, kk = c + 4b, i = chunk/4, j = (chunk%4)*8 + kk
// +1 zero pad chunk so the final prefetch is always legal.
__device__ float g_Wp[(N_CHUNKS + 1) * 512];   // 258 KB

static __device__ __forceinline__ uint32_t f32_to_tf32_rn(float x) {
    uint32_t r;
    asm("cvt.rn.tf32.f32 %0, %1;" : "=r"(r) : "f"(x));
    return r;
}

// ---------------------------------------------------------------------------
__global__ void etp_pack_kernel(const float* __restrict__ Mx) {
    int idx = blockIdx.x * blockDim.x + threadIdx.x;   // 0..66047
    if (idx >= N_CHUNKS * 512) {                       // zero the pad chunk
        if (idx < (N_CHUNKS + 1) * 512) g_Wp[idx] = 0.0f;
        return;
    }
    int chunk = idx >> 9;
    int rem   = idx & 511;
    int nhalf = rem >> 8;
    int r2    = rem & 255;
    int pair  = r2 >> 7;
    int r3    = r2 & 127;
    int lane  = r3 >> 2;
    int sl    = r3 & 3;
    int slot  = pair * 4 + sl;
    int nt    = slot >> 1;
    int b     = slot & 1;
    int qr    = lane >> 2;
    int c     = lane & 3;
    int n     = nhalf * 32 + nt * 8 + qr;
    int kk    = c + 4 * b;
    int i     = chunk >> 2;
    int j     = ((chunk & 3) << 3) + kk;
    float v = Mx[n * (N_I * N_J) + i * N_J + j];
    g_Wp[idx] = __uint_as_float(f32_to_tf32_rn(v));
}

// ---------------------------------------------------------------------------

#define MMA_TF32(cacc, a0, a1, a2, a3, b0, b1)                                \
    asm volatile(                                                             \
        "mma.sync.aligned.m16n8k8.row.col.f32.tf32.tf32.f32 "                 \
        "{%0,%1,%2,%3}, {%4,%5,%6,%7}, {%8,%9}, {%0,%1,%2,%3};"               \
        : "+f"((cacc)[0]), "+f"((cacc)[1]), "+f"((cacc)[2]), "+f"((cacc)[3])  \
        : "r"(a0), "r"(a1), "r"(a2), "r"(a3), "r"(b0), "r"(b1))

__global__ void __launch_bounds__(NTHREADS, 2)
etp_mma_kernel(const float* __restrict__ F1,
               const float* __restrict__ F2,
               float* __restrict__ Out) {
    // padded rows (36 floats) -> conflict-free column reads
    __shared__ float f1s[Z_CTA * 36];
    __shared__ float f2s[Z_CTA * 36];

    const int tid    = threadIdx.x;
    const int warp   = tid >> 5;
    const int lane   = tid & 31;
    const int mgroup = warp >> 1;        // 0..3, 32 rows each
    const int nhalf  = warp & 1;         // n columns [nhalf*32, +32)
    const int qr     = lane >> 2;        // 0..7
    const int c      = lane & 3;         // 0..3

    // ---- stage f1, f2 tiles (coalesced float4) ----
    {
        const float4* f1g = reinterpret_cast<const float4*>(
            F1 + (size_t)blockIdx.x * Z_CTA * N_I);
        const float4* f2g = reinterpret_cast<const float4*>(
            F2 + (size_t)blockIdx.x * Z_CTA * N_J);
#pragma unroll
        for (int t = 0; t < 4; t++) {
            int i4 = tid + t * NTHREADS;          // 0..1023
            int row = i4 >> 3, cg = i4 & 7;
            *reinterpret_cast<float4*>(&f1s[row * 36 + cg * 4]) = __ldg(f1g + i4);
            *reinterpret_cast<float4*>(&f2s[row * 36 + cg * 4]) = __ldg(f2g + i4);
        }
    }
    __syncthreads();

    // thread's 4 z rows (local)
    const int r0 = mgroup * 32 + qr;     // rows r0, r0+8, r0+16, r0+24

    // ---- f2 slots in registers: slot s=cg*2+h -> j = 8*cg + c + 4*h ----
    float f2v[4][8];
#pragma unroll
    for (int rr = 0; rr < 4; rr++) {
#pragma unroll
        for (int s = 0; s < 8; s++) {
            int cg = s >> 1, h = s & 1;
            int j = 8 * cg + c + 4 * h;
            f2v[rr][s] = f2s[(r0 + rr * 8) * 36 + j];
        }
    }

    float C[2][4][4];                    // [mtile][ntile][quad]
#pragma unroll
    for (int mt = 0; mt < 2; mt++)
#pragma unroll
        for (int nt = 0; nt < 4; nt++)
#pragma unroll
            for (int q = 0; q < 4; q++) C[mt][nt][q] = 0.0f;

    // ---- B stream: 2x lane-contiguous LDG.128 per chunk ----
    const float4* wq = reinterpret_cast<const float4*>(g_Wp)
                       + nhalf * 64 + lane;
    float4 bA = __ldg(wq);               // pair 0: n-tiles 0,1
    float4 bB = __ldg(wq + 32);          // pair 1: n-tiles 2,3

#pragma unroll 1
    for (int ig = 0; ig < N_I; ig++) {
        float f1v[4];
#pragma unroll
        for (int rr = 0; rr < 4; rr++) f1v[rr] = f1s[(r0 + rr * 8) * 36 + ig];

#pragma unroll
        for (int cc = 0; cc < 4; cc++) {
            const float4 b0 = bA, b1 = bB;

            wq += 128;                           // next chunk (pad keeps it legal)
            bA = __ldg(wq);
            bB = __ldg(wq + 32);

            // A fragments: raw f32 product bits (HW truncates to tf32)
            uint32_t pr[4][2];
#pragma unroll
            for (int rr = 0; rr < 4; rr++) {
                pr[rr][0] = __float_as_uint(f1v[rr] * f2v[rr][cc * 2 + 0]);
                pr[rr][1] = __float_as_uint(f1v[rr] * f2v[rr][cc * 2 + 1]);
            }

            // mtile0: rows r0, r0+8
            MMA_TF32(C[0][0], pr[0][0], pr[1][0], pr[0][1], pr[1][1],
                     __float_as_uint(b0.x), __float_as_uint(b0.y));
            MMA_TF32(C[0][1], pr[0][0], pr[1][0], pr[0][1], pr[1][1],
                     __float_as_uint(b0.z), __float_as_uint(b0.w));
            MMA_TF32(C[0][2], pr[0][0], pr[1][0], pr[0][1], pr[1][1],
                     __float_as_uint(b1.x), __float_as_uint(b1.y));
            MMA_TF32(C[0][3], pr[0][0], pr[1][0], pr[0][1], pr[1][1],
                     __float_as_uint(b1.z), __float_as_uint(b1.w));
            // mtile1: rows r0+16, r0+24
            MMA_TF32(C[1][0], pr[2][0], pr[3][0], pr[2][1], pr[3][1],
                     __float_as_uint(b0.x), __float_as_uint(b0.y));
            MMA_TF32(C[1][1], pr[2][0], pr[3][0], pr[2][1], pr[3][1],
                     __float_as_uint(b0.z), __float_as_uint(b0.w));
            MMA_TF32(C[1][2], pr[2][0], pr[3][0], pr[2][1], pr[3][1],
                     __float_as_uint(b1.x), __float_as_uint(b1.y));
            MMA_TF32(C[1][3], pr[2][0], pr[3][0], pr[2][1], pr[3][1],
                     __float_as_uint(b1.z), __float_as_uint(b1.w));
        }
    }

    // ---- epilogue ----
    const size_t zbase = (size_t)blockIdx.x * Z_CTA;
#pragma unroll
    for (int mt = 0; mt < 2; mt++) {
        const size_t z0 = zbase + r0 + mt * 16;
        const size_t z1 = z0 + 8;
#pragma unroll
        for (int nt = 0; nt < 4; nt++) {
            const int col = nhalf * 32 + nt * 8 + 2 * c;
            *reinterpret_cast<float2*>(Out + z0 * N_K + col) =
                make_float2(C[mt][nt][0], C[mt][nt][1]);
            *reinterpret_cast<float2*>(Out + z1 * N_K + col) =
                make_float2(C[mt][nt][2], C[mt][nt][3]);
        }
    }
}

// ---------------------------------------------------------------------------

extern "C" void kernel_launch(void* const* d_in, const int* in_sizes, int n_in,
                              void* d_out, int out_size) {
    const float* f1 = (const float*)d_in[0];   // [Z, 32]
    const float* f2 = (const float*)d_in[1];   // [Z, 32]
    const float* mx = (const float*)d_in[2];   // [64, 32, 32]
    float* out = (float*)d_out;                // [Z, 64]

    const int z_total = in_sizes[0] / N_I;     // 131072
    const int blocks = z_total / Z_CTA;        // 1024

    etp_pack_kernel<<<259, 256>>>(mx);         // covers 66048 incl. pad
    etp_mma_kernel<<<blocks, NTHREADS>>>(f1, f2, out);
}

// round 7
// speedup vs baseline: 2.2750x; 1.3542x over previous
#include <cuda_runtime.h>
#include <cuda_fp16.h>
#include <cstdint>

// ============================================================================
// out[z,k] = sum_{i,j} M[k,i,j] * f1[z,i] * f2[z,j]
// Dense fp16 warp-MMA GEMM (fp32 accum):  out = P @ W
//   P[z, i*32+j] = f1[z,i]*f2[z,j]  (fp32 product, cvt.rn -> fp16, in regs)
//   W[i*32+j, k] = M[k,i,j]         (pre-packed fp16x2 fragment order, RN)
//
// R7 = R6 with mma.m16n8k16.f16 (2x FLOP/instr vs tf32 m16n8k8):
//   - MMA instruction count halves -> tensor-busy ~56us -> ~28us
//   - B stream bytes halve (fp16)
//   - precision: fp16 signif == tf32 signif (11 bits); products now RN
//     (better than the R6 truncation) -> rel_err expected ~3e-4
// ============================================================================

#define N_I 32
#define N_J 32
#define N_K 64
#define Z_CTA 128              // 4 m-groups x 32 rows
#define NTHREADS 256           // 8 warps = 4 m-groups x 2 n-halves
#define N_CHUNKS 64            // K = 1024 / 16

// Packed W (uint32 = fp16x2):
//   uint32 offset = chunk*512 + nhalf*256 + pair*128 + lane*4 + slot
//   slot = nt_local*2 + breg   (nt = pair*2 + nt_local)
//   value = {lo = f16rn(M[n,i,j0]), hi = f16rn(M[n,i,j0+1])}
//   n = nhalf*32 + nt*8 + qr ; kk0 = 2c + 8*breg ; i = chunk/2 ;
//   j0 = (chunk&1)*16 + kk0          (lane: qr = lane/4, c = lane%4)
// +1 zero pad chunk so the last prefetch is legal.
__device__ uint32_t g_Wp[(N_CHUNKS + 1) * 512];   // 133 KB

// ---------------------------------------------------------------------------
__global__ void etp_pack_kernel(const float* __restrict__ Mx) {
    int idx = blockIdx.x * blockDim.x + threadIdx.x;   // 0..33279
    if (idx >= N_CHUNKS * 512) {                       // zero the pad chunk
        g_Wp[idx] = 0u;
        return;
    }
    int chunk = idx >> 9;
    int rem   = idx & 511;
    int nhalf = rem >> 8;
    int r2    = rem & 255;
    int pair  = r2 >> 7;
    int r3    = r2 & 127;
    int lane  = r3 >> 2;
    int slot  = r3 & 3;
    int ntl   = slot >> 1;
    int breg  = slot & 1;
    int qr    = lane >> 2;
    int c     = lane & 3;
    int n     = nhalf * 32 + (pair * 2 + ntl) * 8 + qr;
    int i     = chunk >> 1;
    int j0    = ((chunk & 1) << 4) + 2 * c + 8 * breg;
    float v0 = Mx[n * (N_I * N_J) + i * N_J + j0];
    float v1 = Mx[n * (N_I * N_J) + i * N_J + j0 + 1];
    __half2 h = __floats2half2_rn(v0, v1);             // lo=v0, hi=v1
    g_Wp[idx] = *reinterpret_cast<uint32_t*>(&h);
}

// ---------------------------------------------------------------------------

// d = fp16x2{ lo = rn(lo), hi = rn(hi) }
#define CVT_F16X2(d, hi, lo) \
    asm("cvt.rn.f16x2.f32 %0, %1, %2;" : "=r"(d) : "f"(hi), "f"(lo))

#define MMA_F16(cacc, a0, a1, a2, a3, b0, b1)                                 \
    asm volatile(                                                             \
        "mma.sync.aligned.m16n8k16.row.col.f32.f16.f16.f32 "                  \
        "{%0,%1,%2,%3}, {%4,%5,%6,%7}, {%8,%9}, {%0,%1,%2,%3};"               \
        : "+f"((cacc)[0]), "+f"((cacc)[1]), "+f"((cacc)[2]), "+f"((cacc)[3])  \
        : "r"(a0), "r"(a1), "r"(a2), "r"(a3), "r"(b0), "r"(b1))

__global__ void __launch_bounds__(NTHREADS, 2)
etp_mma_kernel(const float* __restrict__ F1,
               const float* __restrict__ F2,
               float* __restrict__ Out) {
    // padded rows (36 floats) -> (near) conflict-free column reads
    __shared__ float f1s[Z_CTA * 36];
    __shared__ float f2s[Z_CTA * 36];

    const int tid    = threadIdx.x;
    const int warp   = tid >> 5;
    const int lane   = tid & 31;
    const int mgroup = warp >> 1;        // 0..3, 32 rows each
    const int nhalf  = warp & 1;         // n columns [nhalf*32, +32)
    const int qr     = lane >> 2;        // 0..7
    const int c      = lane & 3;         // 0..3

    // ---- stage f1, f2 tiles (coalesced float4) ----
    {
        const float4* f1g = reinterpret_cast<const float4*>(
            F1 + (size_t)blockIdx.x * Z_CTA * N_I);
        const float4* f2g = reinterpret_cast<const float4*>(
            F2 + (size_t)blockIdx.x * Z_CTA * N_J);
#pragma unroll
        for (int t = 0; t < 4; t++) {
            int i4 = tid + t * NTHREADS;          // 0..1023
            int row = i4 >> 3, cg = i4 & 7;
            *reinterpret_cast<float4*>(&f1s[row * 36 + cg * 4]) = __ldg(f1g + i4);
            *reinterpret_cast<float4*>(&f2s[row * 36 + cg * 4]) = __ldg(f2g + i4);
        }
    }
    __syncthreads();

    // thread's 4 z rows (local)
    const int r0 = mgroup * 32 + qr;     // rows r0, r0+8, r0+16, r0+24

    // ---- f2 slots: s = jh*4 + breg*2 + par -> j = jh*16 + breg*8 + 2c + par
    float f2v[4][8];
#pragma unroll
    for (int rr = 0; rr < 4; rr++) {
#pragma unroll
        for (int s = 0; s < 8; s++) {
            int jh = s >> 2, breg = (s >> 1) & 1, par = s & 1;
            int j = jh * 16 + breg * 8 + 2 * c + par;
            f2v[rr][s] = f2s[(r0 + rr * 8) * 36 + j];
        }
    }

    float C[2][4][4];                    // [mtile][ntile][quad]
#pragma unroll
    for (int mt = 0; mt < 2; mt++)
#pragma unroll
        for (int nt = 0; nt < 4; nt++)
#pragma unroll
            for (int q = 0; q < 4; q++) C[mt][nt][q] = 0.0f;

    // ---- B stream: 2x lane-contiguous LDG.128 per k16 chunk ----
    const uint4* wq = reinterpret_cast<const uint4*>(g_Wp)
                      + nhalf * 64 + lane;
    uint4 bA = __ldg(wq);                // pair 0: n-tiles 0,1
    uint4 bB = __ldg(wq + 32);           // pair 1: n-tiles 2,3

#pragma unroll 1
    for (int ig = 0; ig < N_I; ig++) {
        float f1v[4];
#pragma unroll
        for (int rr = 0; rr < 4; rr++) f1v[rr] = f1s[(r0 + rr * 8) * 36 + ig];

#pragma unroll
        for (int jh = 0; jh < 2; jh++) {
            const uint4 b0 = bA, b1 = bB;

            wq += 128;                           // next chunk (pad keeps it legal)
            bA = __ldg(wq);
            bB = __ldg(wq + 32);

            // A fragments: fp32 products -> rn fp16x2
            uint32_t a[2][4];
#pragma unroll
            for (int mt = 0; mt < 2; mt++) {
                const float fa = f1v[2 * mt];
                const float fb = f1v[2 * mt + 1];
                const float* va = f2v[2 * mt];
                const float* vb = f2v[2 * mt + 1];
                CVT_F16X2(a[mt][0], fa * va[jh * 4 + 1], fa * va[jh * 4 + 0]);
                CVT_F16X2(a[mt][1], fb * vb[jh * 4 + 1], fb * vb[jh * 4 + 0]);
                CVT_F16X2(a[mt][2], fa * va[jh * 4 + 3], fa * va[jh * 4 + 2]);
                CVT_F16X2(a[mt][3], fb * vb[jh * 4 + 3], fb * vb[jh * 4 + 2]);
            }

            // 8 MMAs (2 mtiles x 4 ntiles), K=16 each
#pragma unroll
            for (int mt = 0; mt < 2; mt++) {
                MMA_F16(C[mt][0], a[mt][0], a[mt][1], a[mt][2], a[mt][3], b0.x, b0.y);
                MMA_F16(C[mt][1], a[mt][0], a[mt][1], a[mt][2], a[mt][3], b0.z, b0.w);
                MMA_F16(C[mt][2], a[mt][0], a[mt][1], a[mt][2], a[mt][3], b1.x, b1.y);
                MMA_F16(C[mt][3], a[mt][0], a[mt][1], a[mt][2], a[mt][3], b1.z, b1.w);
            }
        }
    }

    // ---- epilogue ----
    const size_t zbase = (size_t)blockIdx.x * Z_CTA;
#pragma unroll
    for (int mt = 0; mt < 2; mt++) {
        const size_t z0 = zbase + r0 + mt * 16;
        const size_t z1 = z0 + 8;
#pragma unroll
        for (int nt = 0; nt < 4; nt++) {
            const int col = nhalf * 32 + nt * 8 + 2 * c;
            *reinterpret_cast<float2*>(Out + z0 * N_K + col) =
                make_float2(C[mt][nt][0], C[mt][nt][1]);
            *reinterpret_cast<float2*>(Out + z1 * N_K + col) =
                make_float2(C[mt][nt][2], C[mt][nt][3]);
        }
    }
}

// ---------------------------------------------------------------------------

extern "C" void kernel_launch(void* const* d_in, const int* in_sizes, int n_in,
                              void* d_out, int out_size) {
    const float* f1 = (const float*)d_in[0];   // [Z, 32]
    const float* f2 = (const float*)d_in[1];   // [Z, 32]
    const float* mx = (const float*)d_in[2];   // [64, 32, 32]
    float* out = (float*)d_out;                // [Z, 64]

    const int z_total = in_sizes[0] / N_I;     // 131072
    const int blocks = z_total / Z_CTA;        // 1024

    etp_pack_kernel<<<130, 256>>>(mx);         // 130*256 = 33280 incl. pad
    etp_mma_kernel<<<blocks, NTHREADS>>>(f1, f2, out);
}

// round 8
// speedup vs baseline: 2.6488x; 1.1643x over previous
#include <cuda_runtime.h>
#include <cuda_fp16.h>
#include <cstdint>

// ============================================================================
// out[z,k] = sum_{i,j} M[k,i,j] * f1[z,i] * f2[z,j]
// Dense fp16 warp-MMA GEMM (fp32 accum):  out = P @ W
//   P[z, i*32+j] = f1[z,i]*f2[z,j]  (HMUL2 of pre-converted fp16 operands)
//   W[i*32+j, k] = M[k,i,j]         (pre-packed fp16x2 fragment order, RN)
//
// R8 = R7 with:
//   - f2 held as fp16x2 pair registers (16 u32), f1 staged in smem as
//     broadcast half2(v,v) words -> A fragment = ONE mul.rn.f16x2
//     (was 2 FMUL + 1 CVT): -16 issue slots/chunk, -24 registers
//   - launch_bounds(256,3): 24 warps/SM
// ============================================================================

#define N_I 32
#define N_J 32
#define N_K 64
#define Z_CTA 128              // 4 m-groups x 32 rows
#define NTHREADS 256           // 8 warps = 4 m-groups x 2 n-halves
#define N_CHUNKS 64            // K = 1024 / 16

// Packed W (uint32 = fp16x2): same layout as R7 (validated):
//   uint32 offset = chunk*512 + nhalf*256 + pair*128 + lane*4 + slot
//   slot = nt_local*2 + breg ; n = nhalf*32 + (pair*2+ntl)*8 + qr
//   i = chunk/2 ; j0 = (chunk&1)*16 + 2c + 8*breg ; value = {f16(j0), f16(j0+1)}
__device__ uint32_t g_Wp[(N_CHUNKS + 1) * 512];   // 133 KB (+pad chunk)

// ---------------------------------------------------------------------------
__global__ void etp_pack_kernel(const float* __restrict__ Mx) {
    int idx = blockIdx.x * blockDim.x + threadIdx.x;   // 0..33279
    if (idx >= N_CHUNKS * 512) {
        g_Wp[idx] = 0u;
        return;
    }
    int chunk = idx >> 9;
    int rem   = idx & 511;
    int nhalf = rem >> 8;
    int r2    = rem & 255;
    int pair  = r2 >> 7;
    int r3    = r2 & 127;
    int lane  = r3 >> 2;
    int slot  = r3 & 3;
    int ntl   = slot >> 1;
    int breg  = slot & 1;
    int qr    = lane >> 2;
    int c     = lane & 3;
    int n     = nhalf * 32 + (pair * 2 + ntl) * 8 + qr;
    int i     = chunk >> 1;
    int j0    = ((chunk & 1) << 4) + 2 * c + 8 * breg;
    float v0 = Mx[n * (N_I * N_J) + i * N_J + j0];
    float v1 = Mx[n * (N_I * N_J) + i * N_J + j0 + 1];
    __half2 h = __floats2half2_rn(v0, v1);             // lo=v0, hi=v1
    g_Wp[idx] = *reinterpret_cast<uint32_t*>(&h);
}

// ---------------------------------------------------------------------------

#define HMUL2(d, x, y) \
    asm("mul.rn.f16x2 %0, %1, %2;" : "=r"(d) : "r"(x), "r"(y))

#define MMA_F16(cacc, a0, a1, a2, a3, b0, b1)                                 \
    asm volatile(                                                             \
        "mma.sync.aligned.m16n8k16.row.col.f32.f16.f16.f32 "                  \
        "{%0,%1,%2,%3}, {%4,%5,%6,%7}, {%8,%9}, {%0,%1,%2,%3};"               \
        : "+f"((cacc)[0]), "+f"((cacc)[1]), "+f"((cacc)[2]), "+f"((cacc)[3])  \
        : "r"(a0), "r"(a1), "r"(a2), "r"(a3), "r"(b0), "r"(b1))

__global__ void __launch_bounds__(NTHREADS, 3)
etp_mma_kernel(const float* __restrict__ F1,
               const float* __restrict__ F2,
               float* __restrict__ Out) {
    // f1 as broadcast half2(v,v) words, row stride 33 -> conflict-free col read
    __shared__ uint32_t f1h[Z_CTA * 33];
    // f2 as fp16 adjacent pairs, row stride 17 (init-only reads)
    __shared__ uint32_t f2p[Z_CTA * 17];

    const int tid    = threadIdx.x;
    const int warp   = tid >> 5;
    const int lane   = tid & 31;
    const int mgroup = warp >> 1;        // 0..3, 32 rows each
    const int nhalf  = warp & 1;         // n columns [nhalf*32, +32)
    const int qr     = lane >> 2;        // 0..7
    const int c      = lane & 3;         // 0..3

    // ---- stage tiles ----
    {
        const float4* f1g = reinterpret_cast<const float4*>(
            F1 + (size_t)blockIdx.x * Z_CTA * N_I);
        const float4* f2g = reinterpret_cast<const float4*>(
            F2 + (size_t)blockIdx.x * Z_CTA * N_J);
#pragma unroll
        for (int t = 0; t < 4; t++) {
            int i4 = tid + t * NTHREADS;          // 0..1023
            int row = i4 >> 3, cg = i4 & 7;
            float4 v1 = __ldg(f1g + i4);
            // broadcast pairs (v,v)
            {
                __half2 h0 = __half2half2(__float2half_rn(v1.x));
                __half2 h1 = __half2half2(__float2half_rn(v1.y));
                __half2 h2 = __half2half2(__float2half_rn(v1.z));
                __half2 h3 = __half2half2(__float2half_rn(v1.w));
                uint32_t* p = &f1h[row * 33 + cg * 4];
                p[0] = *reinterpret_cast<uint32_t*>(&h0);
                p[1] = *reinterpret_cast<uint32_t*>(&h1);
                p[2] = *reinterpret_cast<uint32_t*>(&h2);
                p[3] = *reinterpret_cast<uint32_t*>(&h3);
            }
            float4 v2 = __ldg(f2g + i4);
            {
                __half2 ha = __floats2half2_rn(v2.x, v2.y);
                __half2 hb = __floats2half2_rn(v2.z, v2.w);
                uint32_t* p = &f2p[row * 17 + cg * 2];
                p[0] = *reinterpret_cast<uint32_t*>(&ha);
                p[1] = *reinterpret_cast<uint32_t*>(&hb);
            }
        }
    }
    __syncthreads();

    // thread's 4 z rows (local)
    const int r0 = mgroup * 32 + qr;     // rows r0, r0+8, r0+16, r0+24

    // ---- f2 pair regs: s2 = jh*2 + breg -> pair (j0, j0+1), j0 = jh*16+breg*8+2c
    uint32_t f2h[4][4];
#pragma unroll
    for (int rr = 0; rr < 4; rr++) {
#pragma unroll
        for (int s2 = 0; s2 < 4; s2++) {
            int jh = s2 >> 1, breg = s2 & 1;
            int jj = jh * 8 + breg * 4 + c;      // pair index = j0/2
            f2h[rr][s2] = f2p[(r0 + rr * 8) * 17 + jj];
        }
    }

    float C[2][4][4];                    // [mtile][ntile][quad]
#pragma unroll
    for (int mt = 0; mt < 2; mt++)
#pragma unroll
        for (int nt = 0; nt < 4; nt++)
#pragma unroll
            for (int q = 0; q < 4; q++) C[mt][nt][q] = 0.0f;

    // ---- B stream: 2x lane-contiguous LDG.128 per k16 chunk ----
    const uint4* wq = reinterpret_cast<const uint4*>(g_Wp)
                      + nhalf * 64 + lane;
    uint4 bA = __ldg(wq);                // pair 0: n-tiles 0,1
    uint4 bB = __ldg(wq + 32);           // pair 1: n-tiles 2,3

#pragma unroll 1
    for (int ig = 0; ig < N_I; ig++) {
        uint32_t f1v[4];
#pragma unroll
        for (int rr = 0; rr < 4; rr++) f1v[rr] = f1h[(r0 + rr * 8) * 33 + ig];

#pragma unroll
        for (int jh = 0; jh < 2; jh++) {
            const uint4 b0 = bA, b1 = bB;

            wq += 128;                           // next chunk (pad keeps it legal)
            bA = __ldg(wq);
            bB = __ldg(wq + 32);

            // A fragments: one HMUL2 each
            uint32_t a[2][4];
#pragma unroll
            for (int mt = 0; mt < 2; mt++) {
                HMUL2(a[mt][0], f1v[2 * mt],     f2h[2 * mt][jh * 2 + 0]);
                HMUL2(a[mt][1], f1v[2 * mt + 1], f2h[2 * mt + 1][jh * 2 + 0]);
                HMUL2(a[mt][2], f1v[2 * mt],     f2h[2 * mt][jh * 2 + 1]);
                HMUL2(a[mt][3], f1v[2 * mt + 1], f2h[2 * mt + 1][jh * 2 + 1]);
            }

            // 8 MMAs (2 mtiles x 4 ntiles), K=16 each
#pragma unroll
            for (int mt = 0; mt < 2; mt++) {
                MMA_F16(C[mt][0], a[mt][0], a[mt][1], a[mt][2], a[mt][3], b0.x, b0.y);
                MMA_F16(C[mt][1], a[mt][0], a[mt][1], a[mt][2], a[mt][3], b0.z, b0.w);
                MMA_F16(C[mt][2], a[mt][0], a[mt][1], a[mt][2], a[mt][3], b1.x, b1.y);
                MMA_F16(C[mt][3], a[mt][0], a[mt][1], a[mt][2], a[mt][3], b1.z, b1.w);
            }
        }
    }

    // ---- epilogue ----
    const size_t zbase = (size_t)blockIdx.x * Z_CTA;
#pragma unroll
    for (int mt = 0; mt < 2; mt++) {
        const size_t z0 = zbase + r0 + mt * 16;
        const size_t z1 = z0 + 8;
#pragma unroll
        for (int nt = 0; nt < 4; nt++) {
            const int col = nhalf * 32 + nt * 8 + 2 * c;
            *reinterpret_cast<float2*>(Out + z0 * N_K + col) =
                make_float2(C[mt][nt][0], C[mt][nt][1]);
            *reinterpret_cast<float2*>(Out + z1 * N_K + col) =
                make_float2(C[mt][nt][2], C[mt][nt][3]);
        }
    }
}

// ---------------------------------------------------------------------------

extern "C" void kernel_launch(void* const* d_in, const int* in_sizes, int n_in,
                              void* d_out, int out_size) {
    const float* f1 = (const float*)d_in[0];   // [Z, 32]
    const float* f2 = (const float*)d_in[1];   // [Z, 32]
    const float* mx = (const float*)d_in[2];   // [64, 32, 32]
    float* out = (float*)d_out;                // [Z, 64]

    const int z_total = in_sizes[0] / N_I;     // 131072
    const int blocks = z_total / Z_CTA;        // 1024

    etp_pack_kernel<<<130, 256>>>(mx);         // 130*256 = 33280 incl. pad
    etp_mma_kernel<<<blocks, NTHREADS>>>(f1, f2, out);
}